// round 17
// baseline (speedup 1.0000x reference)
#include <cuda_runtime.h>
#include <cuda_fp16.h>
#include <cstdint>

#define NROWS   131072
#define NT      1024          // tiles of 128 rows
#define NPAIR   152           // block pairs
#define GRID    304           // 2 CTAs per SM
#define O_XN2   8388608
#define O_PROTO 16777216
#define O_CVAE  83886080
#define O_PROT  83886081
#define INF_F   __int_as_float(0x7f800000)
#define RPB     432           // ceil(131072/304)

// dynamic smem layout (bytes)
#define OFF_X0   0            // 128 x 64 f32
#define OFF_X1   32768
#define OFF_A    65536        // 128 x 144B fp16 staged
#define OFF_ROW  83968        // 128*9 f32
#define OFF_B2   88576        // 256 f32
#define OFF_RED  89600        // 32 f32 (warp partials + flag)
#define SMEM_SZ  89728

__device__ unsigned g_c1, g_c2;               // monotone ticket counters
__device__ float    g_partial[GRID];
__device__ unsigned g_cmb[GRID * 256];
__device__ float    g_rowpart[2 * NROWS];

__device__ __forceinline__ void mma16816(float* c, const uint32_t* a, uint32_t b0, uint32_t b1) {
    asm volatile(
        "mma.sync.aligned.m16n8k16.row.col.f32.f16.f16.f32 "
        "{%0,%1,%2,%3}, {%4,%5,%6,%7}, {%8,%9}, {%0,%1,%2,%3};"
        : "+f"(c[0]), "+f"(c[1]), "+f"(c[2]), "+f"(c[3])
        : "r"(a[0]), "r"(a[1]), "r"(a[2]), "r"(a[3]), "r"(b0), "r"(b1));
}
__device__ __forceinline__ void ldsm_x4(uint32_t* r, uint32_t addr) {
    asm volatile("ldmatrix.sync.aligned.m8n8.x4.shared.b16 {%0,%1,%2,%3}, [%4];"
        : "=r"(r[0]), "=r"(r[1]), "=r"(r[2]), "=r"(r[3]) : "r"(addr));
}
__device__ __forceinline__ uint32_t smem_u32(const void* p) {
    uint32_t a;
    asm("{ .reg .u64 t; cvta.to.shared.u64 t, %1; cvt.u32.u64 %0, t; }" : "=r"(a) : "l"(p));
    return a;
}
__device__ __forceinline__ uint32_t packh2(float x, float y) {
    __half2 h = __floats2half2_rn(x, y);
    return *reinterpret_cast<uint32_t*>(&h);
}
__device__ __forceinline__ void cp16(uint32_t saddr, const void* gptr) {
    asm volatile("cp.async.ca.shared.global [%0], [%1], 16;" :: "r"(saddr), "l"(gptr) : "memory");
}
#define CP_COMMIT() asm volatile("cp.async.commit_group;" ::: "memory")
#define CP_WAIT0()  asm volatile("cp.async.wait_group 0;" ::: "memory")

__global__ void __launch_bounds__(256, 2)
swav_all(const float* __restrict__ x, const float* __restrict__ W,
         const float* __restrict__ rec, const float* __restrict__ kl,
         const float* __restrict__ mmd, float* __restrict__ out) {
    extern __shared__ __align__(16) unsigned char smem[];
    uint32_t sb = smem_u32(smem);
    float* sRow = (float*)(smem + OFF_ROW);
    float* sB2  = (float*)(smem + OFF_B2);
    float* sRed = (float*)(smem + OFF_RED);

    int tid = threadIdx.x, wid = tid >> 5, lane = tid & 31;
    int g = lane >> 2, t = lane & 3;
    int bid = blockIdx.x, half = bid & 1, pair = bid >> 1;
    int cbase = half * 256;
    int wcol = cbase + wid * 32;          // warp owns cols [wcol, wcol+32)

    // ---- initial prefetch: tile = pair, buffer 0 (8 x 16B per thread) ----
    {
        const char* gp = (const char*)(x + (size_t)pair * 128 * 64);
        #pragma unroll
        for (int q = 0; q < 8; q++)
            cp16(sb + OFF_X0 + (tid + q * 256) * 16, gp + (tid + q * 256) * 16);
        CP_COMMIT();
    }

    // ---- B fragments (this CTA's 256 cols) ----
    uint32_t Bf[4][4][2];
    #pragma unroll
    for (int nt = 0; nt < 4; nt++) {
        int col = wcol + nt * 8 + g;
        #pragma unroll
        for (int ks = 0; ks < 4; ks++) {
            const float2* p = (const float2*)(W + col * 64 + ks * 16) + t;
            float2 v0 = p[0], v1 = p[4];
            Bf[nt][ks][0] = packh2(v0.x, v0.y);
            Bf[nt][ks][1] = packh2(v1.x, v1.y);
        }
    }
    {   // 1 + ||W_k||^2 for this CTA's cols
        const float4* p = (const float4*)(W + (cbase + tid) * 64);
        float s = 0.f;
        #pragma unroll
        for (int i = 0; i < 16; i++) {
            float4 v = p[i];
            s += v.x * v.x + v.y * v.y + v.z * v.z + v.w * v.w;
        }
        sB2[tid] = 1.0f + s;
    }
    __syncthreads();
    float b2[4][2], cmv[4][2];
    #pragma unroll
    for (int nt = 0; nt < 4; nt++) {
        int c0 = wid * 32 + nt * 8 + 2 * t;
        b2[nt][0] = sB2[c0]; b2[nt][1] = sB2[c0 + 1];
        cmv[nt][0] = INF_F;  cmv[nt][1] = INF_F;
    }

    uint32_t aBase = sb + OFF_A;
    uint32_t aLane = (uint32_t)(lane & 15) * 144u + ((lane & 16) ? 16u : 0u);
    float2* xdst = (float2*)(half ? (out + O_XN2) : out);
    int pbuf = 0;

    for (int tile = pair; tile < NT; tile += NPAIR) {
        int rb = tile * 128;
        uint32_t xb = sb + (pbuf ? OFF_X1 : OFF_X0);

        CP_WAIT0();
        __syncthreads();

        int ntile = tile + NPAIR;
        if (ntile < NT) {
            uint32_t xo = sb + (pbuf ? OFF_X0 : OFF_X1);
            const char* gp = (const char*)(x + (size_t)ntile * 128 * 64);
            #pragma unroll
            for (int q = 0; q < 8; q++)
                cp16(xo + (tid + q * 256) * 16, gp + (tid + q * 256) * 16);
        }
        CP_COMMIT();

        // ---- normalize 16 rows/warp; write ONE xn copy; stage fp16 A ----
        #pragma unroll 4
        for (int r = 0; r < 16; r++) {
            int rl = wid * 16 + r;
            int row = rb + rl;
            float2 v;
            asm volatile("ld.shared.v2.f32 {%0,%1}, [%2];"
                : "=f"(v.x), "=f"(v.y) : "r"(xb + (rl * 32 + lane) * 8));
            float s = v.x * v.x + v.y * v.y;
            #pragma unroll
            for (int m = 16; m; m >>= 1) s += __shfl_xor_sync(0xffffffffu, s, m);
            float inv = 1.0f / fmaxf(sqrtf(s), 1e-12f);
            float2 xnv = make_float2(v.x * inv, v.y * inv);
            xdst[(size_t)row * 32 + lane] = xnv;
            asm volatile("st.shared.b32 [%0], %1;"
                :: "r"(aBase + rl * 144u + lane * 4u), "r"(packh2(xnv.x, xnv.y)));
        }
        __syncthreads();

        // ---- 8 rowgroups of 16 rows ----
        #pragma unroll 1
        for (int rg = 0; rg < 8; rg++) {
            uint32_t Af[4][4];
            uint32_t ra = aBase + (uint32_t)rg * (16u * 144u) + aLane;
            #pragma unroll
            for (int ks = 0; ks < 4; ks++) ldsm_x4(Af[ks], ra + ks * 32u);

            float C[4][4];
            #pragma unroll
            for (int nt = 0; nt < 4; nt++)
                C[nt][0] = C[nt][1] = C[nt][2] = C[nt][3] = 0.f;
            #pragma unroll
            for (int ks = 0; ks < 4; ks++)
                #pragma unroll
                for (int nt = 0; nt < 4; nt++)
                    mma16816(C[nt], Af[ks], Bf[nt][ks][0], Bf[nt][ks][1]);

            int r0 = rb + rg * 16 + g, r1 = r0 + 8;
            float rm0 = INF_F, rm1 = INF_F;
            #pragma unroll
            for (int nt = 0; nt < 4; nt++) {
                int c0 = wcol + nt * 8 + 2 * t;
                ((float2*)(out + O_PROTO))[((size_t)r0 * 512 + c0) >> 1] = make_float2(C[nt][0], C[nt][1]);
                ((float2*)(out + O_PROTO))[((size_t)r1 * 512 + c0) >> 1] = make_float2(C[nt][2], C[nt][3]);
                float u00 = fmaxf(fmaf(-2.f, C[nt][0], b2[nt][0]), 1e-12f);
                float u01 = fmaxf(fmaf(-2.f, C[nt][1], b2[nt][1]), 1e-12f);
                float u10 = fmaxf(fmaf(-2.f, C[nt][2], b2[nt][0]), 1e-12f);
                float u11 = fmaxf(fmaf(-2.f, C[nt][3], b2[nt][1]), 1e-12f);
                rm0 = fminf(rm0, fminf(u00, u01));
                rm1 = fminf(rm1, fminf(u10, u11));
                cmv[nt][0] = fminf(cmv[nt][0], fminf(u00, u10));
                cmv[nt][1] = fminf(cmv[nt][1], fminf(u01, u11));
            }
            rm0 = fminf(rm0, __shfl_xor_sync(0xffffffffu, rm0, 1));
            rm0 = fminf(rm0, __shfl_xor_sync(0xffffffffu, rm0, 2));
            rm1 = fminf(rm1, __shfl_xor_sync(0xffffffffu, rm1, 1));
            rm1 = fminf(rm1, __shfl_xor_sync(0xffffffffu, rm1, 2));
            if (t == 0) {
                sRow[(rg * 16 + g) * 9 + wid] = rm0;
                sRow[(rg * 16 + 8 + g) * 9 + wid] = rm1;
            }
        }
        __syncthreads();
        if (tid < 128) {
            float m = sRow[tid * 9];
            #pragma unroll
            for (int w = 1; w < 8; w++) m = fminf(m, sRow[tid * 9 + w]);
            g_rowpart[half * NROWS + rb + tid] = m;   // squared min, this col-half
        }
        pbuf ^= 1;
    }

    // ---- per-block col-min partials ----
    #pragma unroll
    for (int nt = 0; nt < 4; nt++) {
        #pragma unroll
        for (int jj = 0; jj < 2; jj++) {
            float v = cmv[nt][jj];
            v = fminf(v, __shfl_xor_sync(0xffffffffu, v, 4));
            v = fminf(v, __shfl_xor_sync(0xffffffffu, v, 8));
            v = fminf(v, __shfl_xor_sync(0xffffffffu, v, 16));
            if (g == 0)
                g_cmb[bid * 256 + wid * 32 + nt * 8 + 2 * t + jj] = __float_as_uint(v);
        }
    }

    // ---- grid barrier 1 (ticket; all 304 CTAs resident at occ 2) ----
    __threadfence();
    if (tid == 0) {
        unsigned tk = atomicAdd(&g_c1, 1);
        unsigned target = (tk / GRID) * GRID + GRID;
        while (*(volatile unsigned*)&g_c1 < target) {}
    }
    __syncthreads();
    __threadfence();

    // ---- phase 2: parallel row sqrt-sum over slice ----
    float acc = 0.f;
    {
        int start = bid * RPB;
        for (int i = tid; i < RPB; i += 256) {
            int r = start + i;
            if (r < NROWS) {
                float m = fminf(g_rowpart[r], g_rowpart[NROWS + r]);
                acc += sqrtf(m);
            }
        }
    }
    #pragma unroll
    for (int m = 16; m; m >>= 1) acc += __shfl_xor_sync(0xffffffffu, acc, m);
    if (lane == 0) sRed[wid] = acc;
    __syncthreads();
    if (tid == 0) {
        float s = 0.f;
        #pragma unroll
        for (int i = 0; i < 8; i++) s += sRed[i];
        g_partial[bid] = s;
    }
    __threadfence();
    if (tid == 0) {
        unsigned tk = atomicAdd(&g_c2, 1);
        sRed[16] = ((tk % GRID) == (GRID - 1)) ? 1.f : 0.f;
    }
    __syncthreads();

    // ---- last block: finalize ----
    if (sRed[16] != 0.f) {
        __threadfence();
        float* sCol = sRow;                       // reuse (>=512 floats)
        for (int c = tid; c < 512; c += 256) {
            int hh = c >> 8, cc = c & 255;
            float m = INF_F;
            for (int p = 0; p < NPAIR; p++)
                m = fminf(m, __uint_as_float(g_cmb[(2 * p + hh) * 256 + cc]));
            sCol[c] = sqrtf(m);
        }
        __syncthreads();
        if (tid < 256) sCol[tid] += sCol[tid + 256];
        __syncthreads();
        for (int o = 128; o; o >>= 1) {
            if (tid < o) sCol[tid] += sCol[tid + o];
            __syncthreads();
        }
        if (tid == 0) {
            float rs = 0.f;
            for (int i = 0; i < GRID; i++) rs += g_partial[i];
            out[O_PROT] = 0.5f * (rs / (float)NROWS) + 0.5f * (sCol[0] / 512.f);
            out[O_CVAE] = rec[0] + 0.5f * kl[0] + mmd[0];
        }
    }
}

extern "C" void kernel_launch(void* const* d_in, const int* in_sizes, int n_in,
                              void* d_out, int out_size) {
    const float* x   = (const float*)d_in[0];
    const float* W   = (const float*)d_in[1];
    const float* rec = (const float*)d_in[2];
    const float* kl  = (const float*)d_in[3];
    const float* mmd = (const float*)d_in[4];
    float* out = (float*)d_out;
    cudaFuncSetAttribute(swav_all, cudaFuncAttributeMaxDynamicSharedMemorySize, SMEM_SZ);
    swav_all<<<GRID, 256, SMEM_SZ>>>(x, W, rec, kl, mmd, out);
}